// round 1
// baseline (speedup 1.0000x reference)
#include <cuda_runtime.h>

#define BB   8
#define CC   256
#define CQ   32
#define NN   16384
#define TN   64
#define NTIL (NN / TN)      // 256
#define EPSV 1e-6f
#define XPAD 264            // row stride of xsT (floats), 16B-aligned
#define QPAD 65             // row stride of qks

// ---------------- scratch (device globals; no runtime allocation) ----------
__device__ float g_WqkT[CC * 64];                    // [c][o] o<32:Wq, o>=32:Wk
__device__ float g_Qn[(size_t)BB * NN * CQ];         // [b][n][m]
__device__ float g_mp[BB * CQ * CC];                 // Kn @ x^T partials
__device__ float g_S[BB * CQ];                       // sum_n Kn
__device__ float g_xsum[BB * CC];                    // sum_n x
__device__ float g_matrix[BB * CQ * CC];             // [b][m][c]
__device__ float g_vsum[BB * CC];                    // value_sum

// ---------------- kernel 0: zero accumulators + transpose weights ----------
__global__ void k_prep(const float* __restrict__ Wq, const float* __restrict__ Wk) {
    int idx = blockIdx.x * blockDim.x + threadIdx.x;      // 65536 threads
    if (idx < BB * CQ * CC) g_mp[idx] = 0.f;
    if (idx < CC * 64) {
        int c = idx >> 6, o = idx & 63;
        g_WqkT[idx] = (o < 32) ? Wq[o * CC + c] : Wk[(o - 32) * CC + c];
    }
    if (idx < BB * CC) g_xsum[idx] = 0.f;
    if (idx < BB * CQ) g_S[idx] = 0.f;
}

// ---------------- kernel 1: QK projection + norms + Kn@x^T + reductions ----
__global__ void __launch_bounds__(256, 2)
k_qk(const float* __restrict__ x, const float* __restrict__ bq,
     const float* __restrict__ bk) {
    extern __shared__ float sh[];
    float* xsT = sh;                        // [64][XPAD]  x^T tile: [j][c]
    float* qks = sh + TN * XPAD;            // [64][QPAD]  Q/K: [o][j]
    float* rn  = qks + 64 * QPAD;           // [128] rnormQ[0:64], rnormK[64:128]

    const int b   = blockIdx.x >> 8;
    const int n0  = (blockIdx.x & 255) * TN;
    const int tid = threadIdx.x;
    const float* xb = x + (size_t)b * CC * NN;

    // phase 1: stage x tile (coalesced along n), transposed into smem
    for (int idx = tid; idx < CC * TN; idx += 256) {
        int c = idx >> 6, j = idx & 63;
        xsT[j * XPAD + c] = xb[(size_t)c * NN + n0 + j];
    }
    __syncthreads();

    // phase 2: [64o x 64j] = Wqk[64,256] @ xtile[256,64]; 4o x 4j per thread
    {
        const int o0 = (tid & 15) * 4;
        const int j0 = (tid >> 4) * 4;
        float acc[4][4];
        #pragma unroll
        for (int a = 0; a < 4; a++)
            #pragma unroll
            for (int d = 0; d < 4; d++) acc[a][d] = 0.f;

        #pragma unroll 4
        for (int c = 0; c < CC; ++c) {
            float4 w = *(const float4*)&g_WqkT[(c << 6) + o0];
            float x0 = xsT[(j0 + 0) * XPAD + c];
            float x1 = xsT[(j0 + 1) * XPAD + c];
            float x2 = xsT[(j0 + 2) * XPAD + c];
            float x3 = xsT[(j0 + 3) * XPAD + c];
            acc[0][0] += w.x * x0; acc[0][1] += w.x * x1; acc[0][2] += w.x * x2; acc[0][3] += w.x * x3;
            acc[1][0] += w.y * x0; acc[1][1] += w.y * x1; acc[1][2] += w.y * x2; acc[1][3] += w.y * x3;
            acc[2][0] += w.z * x0; acc[2][1] += w.z * x1; acc[2][2] += w.z * x2; acc[2][3] += w.z * x3;
            acc[3][0] += w.w * x0; acc[3][1] += w.w * x1; acc[3][2] += w.w * x2; acc[3][3] += w.w * x3;
        }
        #pragma unroll
        for (int a = 0; a < 4; a++) {
            int o = o0 + a;
            float bias = (o < 32) ? __ldg(&bq[o]) : __ldg(&bk[o - 32]);
            #pragma unroll
            for (int d = 0; d < 4; d++)
                qks[o * QPAD + j0 + d] = acc[a][d] + bias;
        }
    }
    __syncthreads();

    // phase 3: per-column reciprocal L2 norms for Q and K
    if (tid < 128) {
        int qk = tid >> 6, j = tid & 63;
        float s = 0.f;
        #pragma unroll
        for (int o = 0; o < 32; o++) {
            float v = qks[(qk * 32 + o) * QPAD + j];
            s += v * v;
        }
        rn[qk * 64 + j] = rsqrtf(s);
    }
    __syncthreads();

    // phase 4a: xsum partial (column sums of the tile)
    {
        float s = 0.f;
        #pragma unroll
        for (int j = 0; j < TN; j++) s += xsT[j * XPAD + tid];
        atomicAdd(&g_xsum[b * CC + tid], s);
    }
    // phase 4b: S = sum_n Kn partial
    if (tid < 32) {
        float s = 0.f;
        #pragma unroll
        for (int j = 0; j < TN; j++) s += qks[(32 + tid) * QPAD + j] * rn[64 + j];
        atomicAdd(&g_S[b * CQ + tid], s);
    }
    // phase 4c: store Qn [b][n][m] (coalesced 128B groups)
    for (int idx = tid; idx < CQ * TN; idx += 256) {
        int j = idx >> 5, m = idx & 31;
        g_Qn[((size_t)b * NN + n0 + j) * CQ + m] = qks[m * QPAD + j] * rn[j];
    }
    // phase 4d: mp[m][c] += sum_j Kn[m][j] * x[c][j]   (2m x 16c per thread)
    {
        const int mg = tid & 15;
        const int c0 = (tid >> 4) * 16;
        float a0[16], a1[16];
        #pragma unroll
        for (int i = 0; i < 16; i++) { a0[i] = 0.f; a1[i] = 0.f; }

        for (int j = 0; j < TN; ++j) {
            float rk = rn[64 + j];
            float k0 = qks[(32 + mg) * QPAD + j] * rk;
            float k1 = qks[(48 + mg) * QPAD + j] * rk;
            const float* xr = &xsT[j * XPAD + c0];
            #pragma unroll
            for (int q = 0; q < 4; q++) {
                float4 v = *(const float4*)(xr + q * 4);
                a0[q * 4 + 0] += k0 * v.x; a0[q * 4 + 1] += k0 * v.y;
                a0[q * 4 + 2] += k0 * v.z; a0[q * 4 + 3] += k0 * v.w;
                a1[q * 4 + 0] += k1 * v.x; a1[q * 4 + 1] += k1 * v.y;
                a1[q * 4 + 2] += k1 * v.z; a1[q * 4 + 3] += k1 * v.w;
            }
        }
        float* mpb = &g_mp[b * CQ * CC];
        #pragma unroll
        for (int i = 0; i < 16; i++) {
            atomicAdd(&mpb[mg * CC + c0 + i], a0[i]);
            atomicAdd(&mpb[(mg + 16) * CC + c0 + i], a1[i]);
        }
    }
}

// ---------------- kernel 2: matrix = mp @ Wv^T + bv (x) S ; value_sum ------
__global__ void __launch_bounds__(256)
k_mat(const float* __restrict__ Wv, const float* __restrict__ bv) {
    __shared__ float mpT[CC * 36];   // [c][m], pad 36 keeps float4 alignment
    __shared__ float xs_s[CC];
    __shared__ float S_s[CQ];
    const int b = blockIdx.x, tid = threadIdx.x;

    for (int idx = tid; idx < CQ * CC; idx += 256) {
        int m = idx >> 8, c = idx & 255;
        mpT[c * 36 + m] = g_mp[b * CQ * CC + idx];
    }
    xs_s[tid] = g_xsum[b * CC + tid];
    if (tid < 32) S_s[tid] = g_S[b * CQ + tid];
    __syncthreads();

    const int cp = tid;                         // output channel c'
    float bvv = __ldg(&bv[cp]);
    float accm[32];
    #pragma unroll
    for (int m = 0; m < 32; m++) accm[m] = bvv * S_s[m];
    float vs = (float)NN * bvv;

    const float* wrow = Wv + cp * CC;
    for (int c = 0; c < CC; ++c) {
        float w = __ldg(&wrow[c]);
        vs += w * xs_s[c];
        const float4* mr = (const float4*)&mpT[c * 36];
        #pragma unroll
        for (int q = 0; q < 8; q++) {
            float4 v = mr[q];
            accm[q * 4 + 0] += v.x * w; accm[q * 4 + 1] += v.y * w;
            accm[q * 4 + 2] += v.z * w; accm[q * 4 + 3] += v.w * w;
        }
    }
    g_vsum[b * CC + cp] = vs;
    #pragma unroll
    for (int m = 0; m < 32; m++)
        g_matrix[b * CQ * CC + m * CC + cp] = accm[m];
}

// ---------------- kernel 3: epilogue: out = x + g * (vs + Qn@matrix) * tailor
__global__ void __launch_bounds__(256)
k_out(const float* __restrict__ x, const float* __restrict__ gamma,
      float* __restrict__ out) {
    __shared__ float mat_s[CQ * CC];   // [m][c]
    __shared__ float vs_s[CC];
    __shared__ float S_s[CQ];
    const int b   = blockIdx.x >> 8;
    const int n0  = (blockIdx.x & 255) * TN;
    const int tid = threadIdx.x;

    for (int idx = tid; idx < CQ * CC; idx += 256)
        mat_s[idx] = g_matrix[b * CQ * CC + idx];
    vs_s[tid] = g_vsum[b * CC + tid];
    if (tid < 32) S_s[tid] = g_S[b * CQ + tid] + EPSV;   // k_sum = S + eps
    __syncthreads();

    const int j  = tid & 63;
    const int cq = tid >> 6;

    float qn[32];
    const float4* qp = (const float4*)&g_Qn[((size_t)b * NN + n0 + j) * CQ];
    #pragma unroll
    for (int q = 0; q < 8; q++) {
        float4 v = qp[q];
        qn[q * 4 + 0] = v.x; qn[q * 4 + 1] = v.y;
        qn[q * 4 + 2] = v.z; qn[q * 4 + 3] = v.w;
    }
    float tl = 0.f;
    #pragma unroll
    for (int m = 0; m < 32; m++) tl += qn[m] * S_s[m];
    tl = 1.f / ((float)NN + tl);
    const float gt = __ldg(&gamma[0]) * tl;

    const float* xb = x   + (size_t)b * CC * NN + n0 + j;
    float*       ob = out + (size_t)b * CC * NN + n0 + j;

    for (int cb = 0; cb < 16; ++cb) {
        int c0 = cq * 64 + cb * 4;
        float a0 = vs_s[c0 + 0], a1 = vs_s[c0 + 1];
        float a2 = vs_s[c0 + 2], a3 = vs_s[c0 + 3];
        #pragma unroll
        for (int m = 0; m < 32; m++) {
            float4 v = *(const float4*)&mat_s[m * CC + c0];
            float q = qn[m];
            a0 += q * v.x; a1 += q * v.y; a2 += q * v.z; a3 += q * v.w;
        }
        ob[(size_t)(c0 + 0) * NN] = xb[(size_t)(c0 + 0) * NN] + gt * a0;
        ob[(size_t)(c0 + 1) * NN] = xb[(size_t)(c0 + 1) * NN] + gt * a1;
        ob[(size_t)(c0 + 2) * NN] = xb[(size_t)(c0 + 2) * NN] + gt * a2;
        ob[(size_t)(c0 + 3) * NN] = xb[(size_t)(c0 + 3) * NN] + gt * a3;
    }
}

// ---------------- launch --------------------------------------------------
extern "C" void kernel_launch(void* const* d_in, const int* in_sizes, int n_in,
                              void* d_out, int out_size) {
    const float* x     = (const float*)d_in[0];
    const float* Wq    = (const float*)d_in[1];
    const float* bq    = (const float*)d_in[2];
    const float* Wk    = (const float*)d_in[3];
    const float* bk    = (const float*)d_in[4];
    const float* Wv    = (const float*)d_in[5];
    const float* bv    = (const float*)d_in[6];
    const float* gamma = (const float*)d_in[7];
    float* out = (float*)d_out;

    const int shB = (TN * XPAD + 64 * QPAD + 128) * (int)sizeof(float); // 84736 B
    cudaFuncSetAttribute(k_qk, cudaFuncAttributeMaxDynamicSharedMemorySize, shB);

    k_prep<<<256, 256>>>(Wq, Wk);
    k_qk<<<BB * NTIL, 256, shB>>>(x, bq, bk);
    k_mat<<<BB, 256>>>(Wv, bv);
    k_out<<<BB * NTIL, 256>>>(x, gamma, out);
}

// round 2
// speedup vs baseline: 1.7798x; 1.7798x over previous
#include <cuda_runtime.h>
#include <cstdint>

#define BB   8
#define CC   256
#define CQ   32
#define NN   16384
#define TN   64
#define NTIL (NN / TN)      // 256
#define EPSV 1e-6f

// smem strides (in floats) chosen for conflict-free mma fragment loads
#define XST  76             // xs row stride: 76 mod 32 = 12 -> conflict-free A & B frags
#define QST  68             // qks row stride: 68 mod 32 = 4 -> conflict-free B frags

// ---------------- scratch (device globals) ---------------------------------
__device__ __align__(16) uint32_t g_WtF[4 * 32 * 32 * 4];   // pre-swizzled tf32 A-frags
__device__ __align__(16) float g_Qn[(size_t)BB * NN * CQ];  // [b][n][m] fp32
__device__ float g_mpT[BB * CC * CQ];                       // (Kn @ x^T)^T : [b][c][m]
__device__ float g_S[BB * CQ];                              // sum_n Kn
__device__ float g_xsum[BB * CC];                           // sum_n x
__device__ __align__(16) float g_matrix[BB * CQ * CC];      // [b][m][c]
__device__ float g_vsum[BB * CC];                           // value_sum

__device__ __forceinline__ uint32_t f2tf(float f) {
    uint32_t r; asm("cvt.rna.tf32.f32 %0, %1;" : "=r"(r) : "f"(f)); return r;
}

__device__ __forceinline__ void mma_tf32(float& d0, float& d1, float& d2, float& d3,
                                         uint32_t a0, uint32_t a1, uint32_t a2, uint32_t a3,
                                         uint32_t b0, uint32_t b1) {
    asm volatile(
        "mma.sync.aligned.m16n8k8.row.col.f32.tf32.tf32.f32 "
        "{%0,%1,%2,%3},{%4,%5,%6,%7},{%8,%9},{%0,%1,%2,%3};"
        : "+f"(d0), "+f"(d1), "+f"(d2), "+f"(d3)
        : "r"(a0), "r"(a1), "r"(a2), "r"(a3), "r"(b0), "r"(b1));
}

// ---------------- kernel 0: zero accumulators + build tf32 A-fragments -----
__global__ void k_prep(const float* __restrict__ Wq, const float* __restrict__ Wk) {
    int idx = blockIdx.x * blockDim.x + threadIdx.x;      // 65536 threads
    if (idx < BB * CC * CQ) g_mpT[idx] = 0.f;
    if (idx < 16384) {
        int f    = idx & 3;
        int lane = (idx >> 2) & 31;
        int kk   = (idx >> 7) & 31;
        int wo   = idx >> 12;
        int gid = lane >> 2, tig = lane & 3;
        int o = wo * 16 + gid + (f & 1) * 8;
        int c = kk * 8 + tig + (f >> 1) * 4;
        float v = (o < 32) ? Wq[o * CC + c] : Wk[(o - 32) * CC + c];
        g_WtF[idx] = f2tf(v);
    }
    if (idx < BB * CC) g_xsum[idx] = 0.f;
    if (idx < BB * CQ) g_S[idx] = 0.f;
}

// ---------------- kernel 1: tensor-core pass 1 ------------------------------
// per block: batch b, 64-column n tile.
//   step1: QK[64o x 64j] = Wqk @ x-tile       (mma, A=pre-swizzled W frags, B=xs)
//   norms, rescale K->Kn (tf32), store Qn, S, xsum
//   step3: mpT[256c x 32m] += x-tile @ Kn^T   (mma, A=xs, B=Kn in qks)
__global__ void __launch_bounds__(256, 2)
k_qk2(const float* __restrict__ x, const float* __restrict__ bq,
      const float* __restrict__ bk) {
    extern __shared__ float sh[];
    float* xs  = sh;                        // [256][XST]  x tile (tf32 bits)
    float* qks = sh + CC * XST;             // [64][QST]   Q/K rows (fp32), K->tf32
    float* rn  = qks + 64 * QST;            // [128] rnormQ | rnormK
    uint32_t* xsu  = (uint32_t*)xs;
    uint32_t* qksu = (uint32_t*)qks;

    const int b   = blockIdx.x >> 8;
    const int n0  = (blockIdx.x & 255) * TN;
    const int tid = threadIdx.x;
    const int w    = tid >> 5;
    const int lane = tid & 31;
    const int gid  = lane >> 2;
    const int tig  = lane & 3;
    const float* xb = x + (size_t)b * CC * NN;

    // ---- stage x tile as tf32 (coalesced float4 loads) ----
    for (int idx = tid; idx < CC * 16; idx += 256) {
        int c = idx >> 4, q = idx & 15;
        float4 v = *(const float4*)(xb + (size_t)c * NN + n0 + 4 * q);
        uint4 t;
        t.x = f2tf(v.x); t.y = f2tf(v.y); t.z = f2tf(v.z); t.w = f2tf(v.w);
        *(uint4*)&xsu[c * XST + 4 * q] = t;
    }
    __syncthreads();

    // ---- step1: 64x64x256 GEMM on tensor cores ----
    {
        const int wo = w >> 1;        // o-tile (m16): 0..3
        const int wj = w & 1;         // j half: 0..1
        float d0[4], d1[4], d2[4], d3[4];
        #pragma unroll
        for (int s = 0; s < 4; s++) { d0[s] = d1[s] = d2[s] = d3[s] = 0.f; }

        const uint4* WtF = (const uint4*)g_WtF + (wo * 32) * 32 + lane;
        #pragma unroll 4
        for (int kk = 0; kk < 32; kk++) {
            uint4 a = WtF[kk * 32];
            const int c0 = kk * 8;
            uint32_t bA[4], bB[4];
            #pragma unroll
            for (int s = 0; s < 4; s++) {
                int j = 32 * wj + 8 * s + gid;
                bA[s] = xsu[(c0 + tig) * XST + j];
                bB[s] = xsu[(c0 + 4 + tig) * XST + j];
            }
            #pragma unroll
            for (int s = 0; s < 4; s++)
                mma_tf32(d0[s], d1[s], d2[s], d3[s], a.x, a.y, a.z, a.w, bA[s], bB[s]);
        }
        // add bias, store to qks
        const int o1 = 16 * wo + gid;
        const int o2 = o1 + 8;
        const float bi1 = (o1 < 32) ? __ldg(&bq[o1]) : __ldg(&bk[o1 - 32]);
        const float bi2 = (o2 < 32) ? __ldg(&bq[o2]) : __ldg(&bk[o2 - 32]);
        #pragma unroll
        for (int s = 0; s < 4; s++) {
            int j = 32 * wj + 8 * s + 2 * tig;
            qks[o1 * QST + j]     = d0[s] + bi1;
            qks[o1 * QST + j + 1] = d1[s] + bi1;
            qks[o2 * QST + j]     = d2[s] + bi2;
            qks[o2 * QST + j + 1] = d3[s] + bi2;
        }
    }
    __syncthreads();

    // ---- norms ----
    if (tid < 128) {
        int qk = tid >> 6, j = tid & 63;
        float s = 0.f;
        #pragma unroll
        for (int o = 0; o < 32; o++) {
            float v = qks[(qk * 32 + o) * QST + j];
            s += v * v;
        }
        rn[qk * 64 + j] = rsqrtf(s);
    }
    __syncthreads();

    // ---- Qn store (fp32) + rescale K rows to Kn (tf32, in place) ----
    for (int idx = tid; idx < 2048; idx += 256) {         // Qn: m varies in warp
        int m = idx & 31, j = idx >> 5;
        g_Qn[((size_t)b * NN + n0 + j) * CQ + m] = qks[m * QST + j] * rn[j];
    }
    for (int idx = tid; idx < 2048; idx += 256) {         // Kn: j varies in warp
        int j = idx & 63, m = idx >> 6;
        float v = qks[(32 + m) * QST + j] * rn[64 + j];
        qksu[(32 + m) * QST + j] = f2tf(v);
    }
    __syncthreads();

    // ---- S and xsum partials ----
    if (tid < 32) {
        float s = 0.f;
        #pragma unroll
        for (int j = 0; j < TN; j++) s += qks[(32 + tid) * QST + j];
        atomicAdd(&g_S[b * CQ + tid], s);
    }
    {
        float s = 0.f;
        #pragma unroll
        for (int j = 0; j < TN; j++) s += xs[tid * XST + j];
        atomicAdd(&g_xsum[b * CC + tid], s);
    }

    // ---- step3: mpT[256c x 32m] += x-tile @ Kn^T (k = 64) ----
    {
        float e[2][4][4];
        #pragma unroll
        for (int ct = 0; ct < 2; ct++)
            #pragma unroll
            for (int mt = 0; mt < 4; mt++)
                #pragma unroll
                for (int q = 0; q < 4; q++) e[ct][mt][q] = 0.f;

        #pragma unroll
        for (int kk = 0; kk < 8; kk++) {
            const int j0 = kk * 8;
            uint32_t a[2][4];
            #pragma unroll
            for (int ct = 0; ct < 2; ct++) {
                int c0 = (2 * w + ct) * 16;
                a[ct][0] = xsu[(c0 + gid) * XST + j0 + tig];
                a[ct][1] = xsu[(c0 + 8 + gid) * XST + j0 + tig];
                a[ct][2] = xsu[(c0 + gid) * XST + j0 + 4 + tig];
                a[ct][3] = xsu[(c0 + 8 + gid) * XST + j0 + 4 + tig];
            }
            uint32_t bb0[4], bb1[4];
            #pragma unroll
            for (int mt = 0; mt < 4; mt++) {
                int m0 = mt * 8;
                bb0[mt] = qksu[(32 + m0 + gid) * QST + j0 + tig];
                bb1[mt] = qksu[(32 + m0 + gid) * QST + j0 + 4 + tig];
            }
            #pragma unroll
            for (int ct = 0; ct < 2; ct++)
                #pragma unroll
                for (int mt = 0; mt < 4; mt++)
                    mma_tf32(e[ct][mt][0], e[ct][mt][1], e[ct][mt][2], e[ct][mt][3],
                             a[ct][0], a[ct][1], a[ct][2], a[ct][3], bb0[mt], bb1[mt]);
        }
        float* mpb = &g_mpT[b * CC * CQ];
        #pragma unroll
        for (int ct = 0; ct < 2; ct++) {
            int c0 = (2 * w + ct) * 16;
            #pragma unroll
            for (int mt = 0; mt < 4; mt++) {
                int m0 = mt * 8 + 2 * tig;
                atomicAdd(&mpb[(c0 + gid) * CQ + m0],         e[ct][mt][0]);
                atomicAdd(&mpb[(c0 + gid) * CQ + m0 + 1],     e[ct][mt][1]);
                atomicAdd(&mpb[(c0 + 8 + gid) * CQ + m0],     e[ct][mt][2]);
                atomicAdd(&mpb[(c0 + 8 + gid) * CQ + m0 + 1], e[ct][mt][3]);
            }
        }
    }
}

// ---------------- kernel 2: matrix = mp @ Wv^T + bv (x) S ; value_sum ------
__global__ void __launch_bounds__(256)
k_mat(const float* __restrict__ Wv, const float* __restrict__ bv) {
    __shared__ float mpT[CC * CQ];   // [c][m] — direct copy of g_mpT
    __shared__ float xs_s[CC];
    __shared__ float S_s[CQ];
    const int b = blockIdx.x, tid = threadIdx.x;

    for (int idx = tid; idx < CC * CQ; idx += 256)
        mpT[idx] = g_mpT[b * CC * CQ + idx];
    xs_s[tid] = g_xsum[b * CC + tid];
    if (tid < 32) S_s[tid] = g_S[b * CQ + tid];
    __syncthreads();

    const int cp = tid;
    float bvv = __ldg(&bv[cp]);
    float accm[32];
    #pragma unroll
    for (int m = 0; m < 32; m++) accm[m] = bvv * S_s[m];
    float vs = (float)NN * bvv;

    const float* wrow = Wv + cp * CC;
    for (int c = 0; c < CC; ++c) {
        float wv = __ldg(&wrow[c]);
        vs += wv * xs_s[c];
        const float4* mr = (const float4*)&mpT[c * CQ];
        #pragma unroll
        for (int q = 0; q < 8; q++) {
            float4 v = mr[q];
            accm[q * 4 + 0] += v.x * wv; accm[q * 4 + 1] += v.y * wv;
            accm[q * 4 + 2] += v.z * wv; accm[q * 4 + 3] += v.w * wv;
        }
    }
    g_vsum[b * CC + cp] = vs;
    #pragma unroll
    for (int m = 0; m < 32; m++)
        g_matrix[b * CQ * CC + m * CC + cp] = accm[m];
}

// ---------------- kernel 3: epilogue, 2 n-positions per thread -------------
__global__ void __launch_bounds__(256, 2)
k_out(const float* __restrict__ x, const float* __restrict__ gamma,
      float* __restrict__ out) {
    __shared__ float mat_s[CQ * CC];   // [m][c]
    __shared__ float vs_s[CC];
    __shared__ float S_s[CQ];
    const int b   = blockIdx.x >> 7;
    const int n0  = (blockIdx.x & 127) * 128;
    const int tid = threadIdx.x;

    for (int idx = tid; idx < CQ * CC; idx += 256)
        mat_s[idx] = g_matrix[b * CQ * CC + idx];
    vs_s[tid] = g_vsum[b * CC + tid];
    if (tid < 32) S_s[tid] = g_S[b * CQ + tid] + EPSV;   // k_sum = S + eps
    __syncthreads();

    const int j  = tid & 63;
    const int cq = tid >> 6;

    float qnA[32], qnB[32];
    const float4* qpA = (const float4*)&g_Qn[((size_t)b * NN + n0 + j) * CQ];
    const float4* qpB = (const float4*)&g_Qn[((size_t)b * NN + n0 + 64 + j) * CQ];
    #pragma unroll
    for (int q = 0; q < 8; q++) {
        float4 va = qpA[q], vb = qpB[q];
        qnA[q * 4 + 0] = va.x; qnA[q * 4 + 1] = va.y; qnA[q * 4 + 2] = va.z; qnA[q * 4 + 3] = va.w;
        qnB[q * 4 + 0] = vb.x; qnB[q * 4 + 1] = vb.y; qnB[q * 4 + 2] = vb.z; qnB[q * 4 + 3] = vb.w;
    }
    float tA = 0.f, tB = 0.f;
    #pragma unroll
    for (int m = 0; m < 32; m++) { tA += qnA[m] * S_s[m]; tB += qnB[m] * S_s[m]; }
    const float g  = __ldg(&gamma[0]);
    const float gA = g / ((float)NN + tA);
    const float gB = g / ((float)NN + tB);

    const float* xp = x   + (size_t)b * CC * NN + n0 + j;
    float*       op = out + (size_t)b * CC * NN + n0 + j;

    #pragma unroll 1
    for (int cb = 0; cb < 16; ++cb) {
        const int c0 = cq * 64 + cb * 4;
        float aA0 = vs_s[c0 + 0], aA1 = vs_s[c0 + 1], aA2 = vs_s[c0 + 2], aA3 = vs_s[c0 + 3];
        float aB0 = aA0, aB1 = aA1, aB2 = aA2, aB3 = aA3;
        #pragma unroll
        for (int m = 0; m < 32; m++) {
            float4 v = *(const float4*)&mat_s[m * CC + c0];
            float qa = qnA[m], qb = qnB[m];
            aA0 += qa * v.x; aA1 += qa * v.y; aA2 += qa * v.z; aA3 += qa * v.w;
            aB0 += qb * v.x; aB1 += qb * v.y; aB2 += qb * v.z; aB3 += qb * v.w;
        }
        op[(size_t)(c0 + 0) * NN]      = xp[(size_t)(c0 + 0) * NN]      + gA * aA0;
        op[(size_t)(c0 + 1) * NN]      = xp[(size_t)(c0 + 1) * NN]      + gA * aA1;
        op[(size_t)(c0 + 2) * NN]      = xp[(size_t)(c0 + 2) * NN]      + gA * aA2;
        op[(size_t)(c0 + 3) * NN]      = xp[(size_t)(c0 + 3) * NN]      + gA * aA3;
        op[(size_t)(c0 + 0) * NN + 64] = xp[(size_t)(c0 + 0) * NN + 64] + gB * aB0;
        op[(size_t)(c0 + 1) * NN + 64] = xp[(size_t)(c0 + 1) * NN + 64] + gB * aB1;
        op[(size_t)(c0 + 2) * NN + 64] = xp[(size_t)(c0 + 2) * NN + 64] + gB * aB2;
        op[(size_t)(c0 + 3) * NN + 64] = xp[(size_t)(c0 + 3) * NN + 64] + gB * aB3;
    }
}

// ---------------- launch --------------------------------------------------
extern "C" void kernel_launch(void* const* d_in, const int* in_sizes, int n_in,
                              void* d_out, int out_size) {
    const float* x     = (const float*)d_in[0];
    const float* Wq    = (const float*)d_in[1];
    const float* bq    = (const float*)d_in[2];
    const float* Wk    = (const float*)d_in[3];
    const float* bk    = (const float*)d_in[4];
    const float* Wv    = (const float*)d_in[5];
    const float* bv    = (const float*)d_in[6];
    const float* gamma = (const float*)d_in[7];
    float* out = (float*)d_out;

    const int shB = (CC * XST + 64 * QST + 128) * (int)sizeof(float); // 95744 B
    cudaFuncSetAttribute(k_qk2, cudaFuncAttributeMaxDynamicSharedMemorySize, shB);

    k_prep<<<256, 256>>>(Wq, Wk);
    k_qk2<<<BB * NTIL, 256, shB>>>(x, bq, bk);
    k_mat<<<BB, 256>>>(Wv, bv);
    k_out<<<BB * 128, 256>>>(x, gamma, out);
}